// round 3
// baseline (speedup 1.0000x reference)
#include <cuda_runtime.h>
#include <math.h>

#define NN 8192
#define FF 256
#define NE 262144
#define ADJW (NN * (NN / 32))   // 2,097,152 words = 8 MB bitmap

// ---------------- scratch (device globals; no allocation allowed) ----------------
__device__ __align__(256) float    g_meansum[FF];
__device__ __align__(256) float    g_mean[FF];
__device__ __align__(256) float    g_cov[FF * FF];
__device__ __align__(256) float    g_cor[FF * FF];
__device__ __align__(256) float    g_w[NN];
__device__ __align__(256) float    g_z2[NN * FF];       // 8 MB
__device__ __align__(256) float    g_invn[NN];
__device__ __align__(256) unsigned g_adj[ADJW];          // 8 MB adjacency bitmap
__device__ __align__(256) float    g_scores[NN];
__device__ __align__(256) float    g_deg[NN];
__device__ double g_penalty;                             // total masked sum (x2 upper + diag)
__device__ int    g_is64;                                // 1 if index inputs are int64

// ---------------- index dtype detection (int32 vs int64) ----------------
// If the edge buffer holds int64 values < 2^31, every odd 32-bit word is 0.
// If it holds int32 values uniform in [0,8192), odd words are random nonzero.
__global__ void k_detect(const unsigned* __restrict__ e) {
    unsigned acc = 0;
    for (int i = threadIdx.x; i < 2048; i += 256) acc |= e[2 * i + 1];
    int any = __syncthreads_or((int)(acc != 0));
    if (threadIdx.x == 0) g_is64 = any ? 0 : 1;
}

__device__ __forceinline__ int load_idx(const void* p, int k, int is64) {
    return is64 ? (int)((const long long*)p)[k] : ((const int*)p)[k];
}

// ---------------- zero scratch ----------------
__global__ void k_zero() {
    int idx = blockIdx.x * blockDim.x + threadIdx.x;
    int stride = gridDim.x * blockDim.x;
    for (int i = idx; i < ADJW; i += stride) g_adj[i] = 0u;
    for (int i = idx; i < FF * FF; i += stride) g_cov[i] = 0.0f;
    for (int i = idx; i < NN; i += stride) { g_scores[i] = 0.0f; g_deg[i] = 0.0f; }
    for (int i = idx; i < FF; i += stride) g_meansum[i] = 0.0f;
    if (idx == 0) g_penalty = 0.0;
}

// ---------------- column sums -> mean ----------------
__global__ void k_mean(const float* __restrict__ z) {
    int f = threadIdx.x;                  // 256 threads = one feature each
    int r0 = blockIdx.x * 64;             // 128 blocks * 64 rows
    float s = 0.0f;
    #pragma unroll 8
    for (int r = 0; r < 64; ++r) s += z[(r0 + r) * FF + f];
    atomicAdd(&g_meansum[f], s);
}

__global__ void k_meanfix() {
    g_mean[threadIdx.x] = g_meansum[threadIdx.x] * (1.0f / (float)NN);
}

// ---------------- per-node weight w = 0.9^k2u + 1 - 0.9^u2k ----------------
__global__ void k_w(const void* __restrict__ k2u, const void* __restrict__ u2k) {
    int n = blockIdx.x * blockDim.x + threadIdx.x;
    int is64 = g_is64;
    if (n < NN) {
        float a = powf(0.9f, (float)load_idx(k2u, n, is64));
        float b = powf(0.9f, (float)load_idx(u2k, n, is64));
        g_w[n] = a + 1.0f - b;
    }
}

// ---------------- adjacency bitmap + degree ----------------
__global__ void k_adj(const void* __restrict__ ei) {
    int e = blockIdx.x * blockDim.x + threadIdx.x;
    int is64 = g_is64;
    if (e < NE) {
        int i = load_idx(ei, e, is64);
        int j = load_idx(ei, NE + e, is64);
        unsigned b1 = (unsigned)i * NN + (unsigned)j;
        atomicOr(&g_adj[b1 >> 5], 1u << (b1 & 31));
        unsigned b2 = (unsigned)j * NN + (unsigned)i;
        atomicOr(&g_adj[b2 >> 5], 1u << (b2 & 31));
        atomicAdd(&g_deg[i], 1.0f);
    }
}

// ---------------- cov = zm^T @ zm  (split-K, 64x64 tiles) ----------------
__global__ void k_cov(const float* __restrict__ z) {
    __shared__ float sA[16][68];
    __shared__ float sB[16][68];
    int i0 = blockIdx.x * 64, j0 = blockIdx.y * 64, r0 = blockIdx.z * 512;
    int tid = threadIdx.x;
    int tx = tid & 15, ty = tid >> 4;
    int col = tid & 63;
    int kb = tid >> 6;                     // 0..3
    float meanA = g_mean[i0 + col];
    float meanB = g_mean[j0 + col];
    float acc[4][4] = {};
    for (int rr = 0; rr < 512; rr += 16) {
        __syncthreads();
        #pragma unroll
        for (int l = 0; l < 4; ++l) {
            int kk = kb * 4 + l;
            int r = r0 + rr + kk;
            sA[kk][col] = z[r * FF + i0 + col] - meanA;
            sB[kk][col] = z[r * FF + j0 + col] - meanB;
        }
        __syncthreads();
        #pragma unroll
        for (int kk = 0; kk < 16; ++kk) {
            float a[4], b[4];
            #pragma unroll
            for (int u = 0; u < 4; ++u) a[u] = sA[kk][tx * 4 + u];
            #pragma unroll
            for (int v = 0; v < 4; ++v) b[v] = sB[kk][ty * 4 + v];
            #pragma unroll
            for (int u = 0; u < 4; ++u)
                #pragma unroll
                for (int v = 0; v < 4; ++v) acc[u][v] += a[u] * b[v];
        }
    }
    #pragma unroll
    for (int u = 0; u < 4; ++u)
        #pragma unroll
        for (int v = 0; v < 4; ++v)
            atomicAdd(&g_cov[(i0 + tx * 4 + u) * FF + (j0 + ty * 4 + v)], acc[u][v]);
}

// ---------------- cor = clip(nan_to_num(cov / (std_i std_j))), zero diag ----------------
__global__ void k_cor() {
    int idx = blockIdx.x * blockDim.x + threadIdx.x;
    int i = idx >> 8, j = idx & 255;
    float d = sqrtf(g_cov[i * FF + i]) * sqrtf(g_cov[j * FF + j]);
    float v = g_cov[idx] / d;
    if (v != v) v = 0.0f;                  // nan -> 0; +-inf clipped below
    v = fminf(1.0f, fmaxf(-1.0f, v));
    if (i == j) v = 0.0f;
    g_cor[idx] = v;
}

// ---------------- z2 = z + 0.01 * (w .* zm) @ cor  (128x128 tiles) ----------------
__global__ void k_z2(const float* __restrict__ z) {
    __shared__ float sA[16][132];
    __shared__ float sB[16][132];
    int r0 = blockIdx.x * 128, c0 = blockIdx.y * 128;
    int tid = threadIdx.x;
    int tx = tid & 15, ty = tid >> 4;
    float acc[8][8] = {};
    for (int k0 = 0; k0 < FF; k0 += 16) {
        __syncthreads();
        #pragma unroll
        for (int it = 0; it < 2; ++it) {
            int idx = tid + it * 256;      // 0..511
            int row = idx >> 2, kq = idx & 3;
            float4 zv = *(const float4*)(z + (r0 + row) * FF + k0 + kq * 4);
            float4 mv = *(const float4*)(g_mean + k0 + kq * 4);
            float wv = g_w[r0 + row];
            sA[kq * 4 + 0][row] = wv * (zv.x - mv.x);
            sA[kq * 4 + 1][row] = wv * (zv.y - mv.y);
            sA[kq * 4 + 2][row] = wv * (zv.z - mv.z);
            sA[kq * 4 + 3][row] = wv * (zv.w - mv.w);
            int kk = idx >> 5, nq = idx & 31;
            float4 bv = *(const float4*)(g_cor + (k0 + kk) * FF + c0 + nq * 4);
            *(float4*)&sB[kk][nq * 4] = bv;
        }
        __syncthreads();
        #pragma unroll
        for (int kk = 0; kk < 16; ++kk) {
            float4 a0 = *(const float4*)&sA[kk][ty * 8];
            float4 a1 = *(const float4*)&sA[kk][ty * 8 + 4];
            float4 b0 = *(const float4*)&sB[kk][tx * 8];
            float4 b1 = *(const float4*)&sB[kk][tx * 8 + 4];
            float a[8] = {a0.x, a0.y, a0.z, a0.w, a1.x, a1.y, a1.z, a1.w};
            float b[8] = {b0.x, b0.y, b0.z, b0.w, b1.x, b1.y, b1.z, b1.w};
            #pragma unroll
            for (int u = 0; u < 8; ++u)
                #pragma unroll
                for (int v = 0; v < 8; ++v) acc[u][v] += a[u] * b[v];
        }
    }
    #pragma unroll
    for (int u = 0; u < 8; ++u) {
        int r = r0 + ty * 8 + u;
        #pragma unroll
        for (int v = 0; v < 8; ++v) {
            int c = c0 + tx * 8 + v;
            g_z2[r * FF + c] = z[r * FF + c] + 0.01f * acc[u][v];
        }
    }
}

// ---------------- row norms, inverse norms, and diagonal penalty terms ----------------
__global__ void k_norm() {
    int gw = (blockIdx.x * blockDim.x + threadIdx.x) >> 5;
    int lane = threadIdx.x & 31;
    if (gw >= NN) return;
    const float4* p = (const float4*)(g_z2 + gw * FF);
    float4 a = p[lane * 2], b = p[lane * 2 + 1];
    float s = a.x * a.x + a.y * a.y + a.z * a.z + a.w * a.w
            + b.x * b.x + b.y * b.y + b.z * b.z + b.w * b.w;
    #pragma unroll
    for (int o = 16; o; o >>= 1) s += __shfl_down_sync(0xffffffffu, s, o);
    if (lane == 0) {
        g_invn[gw] = 1.0f / fmaxf(sqrtf(s), 1e-8f);
        unsigned bi = (unsigned)gw * NN + (unsigned)gw;
        unsigned bit = (g_adj[bi >> 5] >> (bi & 31)) & 1u;
        if (s > 0.8f && !bit) atomicAdd(&g_penalty, (double)s);   // sim_mat diagonal
    }
}

// ---------------- per-edge cosine similarity, scatter by source ----------------
__global__ void k_edge(const void* __restrict__ ei) {
    int gw = (blockIdx.x * blockDim.x + threadIdx.x) >> 5;
    int lane = threadIdx.x & 31;
    if (gw >= NE) return;
    int is64 = g_is64;
    int i = load_idx(ei, gw, is64);
    int j = load_idx(ei, NE + gw, is64);
    const float4* pi = (const float4*)(g_z2 + i * FF);
    const float4* pj = (const float4*)(g_z2 + j * FF);
    float4 a0 = pi[lane * 2], a1 = pi[lane * 2 + 1];
    float4 b0 = pj[lane * 2], b1 = pj[lane * 2 + 1];
    float d = a0.x * b0.x + a0.y * b0.y + a0.z * b0.z + a0.w * b0.w
            + a1.x * b1.x + a1.y * b1.y + a1.z * b1.z + a1.w * b1.w;
    #pragma unroll
    for (int o = 16; o; o >>= 1) d += __shfl_down_sync(0xffffffffu, d, o);
    if (lane == 0) atomicAdd(&g_scores[i], d * g_invn[i] * g_invn[j]);
}

// ---------------- masked similarity GEMM over strict upper-triangle tiles ----------------
__device__ __forceinline__ int cumt(int br) { return br * 64 - (br * (br - 1)) / 2; }

__global__ void k_sim() {
    __shared__ float sA[16][132];
    __shared__ float sB[16][132];
    __shared__ unsigned sAdj[512];
    __shared__ float sRed[256];
    int t = blockIdx.x;
    int br = (int)(64.5f - sqrtf(64.5f * 64.5f - 2.0f * (float)t));
    if (br < 0) br = 0; if (br > 63) br = 63;
    while (br < 63 && cumt(br + 1) <= t) br++;
    while (br > 0 && cumt(br) > t) br--;
    int bc = br + (t - cumt(br));
    int r0 = br * 128, c0 = bc * 128;

    int tid = threadIdx.x;
    int tx = tid & 15, ty = tid >> 4;
    float acc[8][8] = {};
    for (int k0 = 0; k0 < FF; k0 += 16) {
        __syncthreads();
        #pragma unroll
        for (int it = 0; it < 2; ++it) {
            int idx = tid + it * 256;
            int row = idx >> 2, kq = idx & 3;
            float4 av = *(const float4*)(g_z2 + (r0 + row) * FF + k0 + kq * 4);
            sA[kq * 4 + 0][row] = av.x;
            sA[kq * 4 + 1][row] = av.y;
            sA[kq * 4 + 2][row] = av.z;
            sA[kq * 4 + 3][row] = av.w;
            float4 bv = *(const float4*)(g_z2 + (c0 + row) * FF + k0 + kq * 4);
            sB[kq * 4 + 0][row] = bv.x;
            sB[kq * 4 + 1][row] = bv.y;
            sB[kq * 4 + 2][row] = bv.z;
            sB[kq * 4 + 3][row] = bv.w;
        }
        __syncthreads();
        #pragma unroll
        for (int kk = 0; kk < 16; ++kk) {
            float4 a0 = *(const float4*)&sA[kk][ty * 8];
            float4 a1 = *(const float4*)&sA[kk][ty * 8 + 4];
            float4 b0 = *(const float4*)&sB[kk][tx * 8];
            float4 b1 = *(const float4*)&sB[kk][tx * 8 + 4];
            float a[8] = {a0.x, a0.y, a0.z, a0.w, a1.x, a1.y, a1.z, a1.w};
            float b[8] = {b0.x, b0.y, b0.z, b0.w, b1.x, b1.y, b1.z, b1.w};
            #pragma unroll
            for (int u = 0; u < 8; ++u)
                #pragma unroll
                for (int v = 0; v < 8; ++v) acc[u][v] += a[u] * b[v];
        }
    }
    // adjacency words for this 128x128 tile (128 rows x 4 words)
    for (int s2 = tid; s2 < 512; s2 += 256)
        sAdj[s2] = g_adj[(r0 + (s2 >> 2)) * (NN / 32) + (c0 >> 5) + (s2 & 3)];
    __syncthreads();

    bool diagBlk = (br == bc);
    float lsum = 0.0f;
    #pragma unroll
    for (int u = 0; u < 8; ++u) {
        int rl = ty * 8 + u;
        #pragma unroll
        for (int v = 0; v < 8; ++v) {
            int cl = tx * 8 + v;
            float val = acc[u][v];
            unsigned bit = (sAdj[rl * 4 + (cl >> 5)] >> (cl & 31)) & 1u;
            if (val > 0.8f && !bit && (!diagBlk || cl > rl)) lsum += val;
        }
    }
    sRed[tid] = lsum;
    __syncthreads();
    for (int o = 128; o; o >>= 1) {
        if (tid < o) sRed[tid] += sRed[tid + o];
        __syncthreads();
    }
    if (tid == 0) atomicAdd(&g_penalty, 2.0 * (double)sRed[0]);  // symmetric: count twice
}

// ---------------- final scalar ----------------
__global__ void k_final(float* __restrict__ out) {
    __shared__ double sred[256];
    int tid = threadIdx.x;
    double s = 0.0;
    for (int n = tid; n < NN; n += 256) {
        float d = g_deg[n];
        if (d == 0.0f) d = 1.0f;
        s += (double)(g_scores[n] / d);
    }
    sred[tid] = s;
    __syncthreads();
    for (int o = 128; o; o >>= 1) {
        if (tid < o) sred[tid] += sred[tid + o];
        __syncthreads();
    }
    if (tid == 0) {
        double hom = -sred[0] / (double)NN;
        double pen = g_penalty / ((double)NN * (double)NN);
        out[0] = (float)(hom + pen);
    }
}

// ---------------- launch ----------------
extern "C" void kernel_launch(void* const* d_in, const int* in_sizes, int n_in,
                              void* d_out, int out_size) {
    const float* z   = (const float*)d_in[0];
    // d_in[1] = x_hat (unused by the loss)
    const void* ei   = d_in[2];
    const void* k2u  = d_in[3];
    const void* u2k  = d_in[4];
    float* out = (float*)d_out;

    k_detect<<<1, 256>>>((const unsigned*)ei);
    k_zero<<<2048, 256>>>();
    k_mean<<<128, 256>>>(z);
    k_meanfix<<<1, 256>>>();
    k_w<<<32, 256>>>(k2u, u2k);
    k_adj<<<NE / 256, 256>>>(ei);
    k_cov<<<dim3(4, 4, 16), 256>>>(z);
    k_cor<<<256, 256>>>();
    k_z2<<<dim3(64, 2), 256>>>(z);
    k_norm<<<NN / 8, 256>>>();
    k_edge<<<NE / 8, 256>>>(ei);
    k_sim<<<2080, 256>>>();
    k_final<<<1, 256>>>(out);
}

// round 4
// speedup vs baseline: 2.2835x; 2.2835x over previous
#include <cuda_runtime.h>
#include <cuda_bf16.h>
#include <math.h>

#define NN 8192
#define FF 256
#define NE 262144
#define ADJW (NN * (NN / 32))   // 2,097,152 words = 8 MB bitmap

// ---------------- scratch (device globals; no allocation allowed) ----------------
__device__ __align__(256) float    g_meansum[FF];
__device__ __align__(256) float    g_mean[FF];
__device__ __align__(256) float    g_cov[FF * FF];
__device__ __align__(256) float    g_cor[FF * FF];
__device__ __align__(256) float    g_w[NN];
__device__ __align__(256) float    g_z2[NN * FF];        // 8 MB fp32
__device__ __align__(256) __nv_bfloat16 g_z2h[NN * FF];  // 4 MB bf16 copy for MMA
__device__ __align__(256) float    g_invn[NN];
__device__ __align__(256) unsigned g_adj[ADJW];          // 8 MB adjacency bitmap
__device__ __align__(256) float    g_scores[NN];
__device__ __align__(256) float    g_deg[NN];
__device__ double g_penalty;                             // total masked sum (x2 upper + diag)
__device__ int    g_is64;                                // 1 if index inputs are int64

// ---------------- index dtype detection (int32 vs int64) ----------------
__global__ void k_detect(const unsigned* __restrict__ e) {
    unsigned acc = 0;
    for (int i = threadIdx.x; i < 2048; i += 256) acc |= e[2 * i + 1];
    int any = __syncthreads_or((int)(acc != 0));
    if (threadIdx.x == 0) g_is64 = any ? 0 : 1;
}

__device__ __forceinline__ int load_idx(const void* p, int k, int is64) {
    return is64 ? (int)((const long long*)p)[k] : ((const int*)p)[k];
}

// ---------------- zero scratch ----------------
__global__ void k_zero() {
    int idx = blockIdx.x * blockDim.x + threadIdx.x;
    int stride = gridDim.x * blockDim.x;
    for (int i = idx; i < ADJW; i += stride) g_adj[i] = 0u;
    for (int i = idx; i < FF * FF; i += stride) g_cov[i] = 0.0f;
    for (int i = idx; i < NN; i += stride) { g_scores[i] = 0.0f; g_deg[i] = 0.0f; }
    for (int i = idx; i < FF; i += stride) g_meansum[i] = 0.0f;
    if (idx == 0) g_penalty = 0.0;
}

// ---------------- column sums -> mean ----------------
__global__ void k_mean(const float* __restrict__ z) {
    int f = threadIdx.x;
    int r0 = blockIdx.x * 64;
    float s = 0.0f;
    #pragma unroll 8
    for (int r = 0; r < 64; ++r) s += z[(r0 + r) * FF + f];
    atomicAdd(&g_meansum[f], s);
}

__global__ void k_meanfix() {
    g_mean[threadIdx.x] = g_meansum[threadIdx.x] * (1.0f / (float)NN);
}

// ---------------- per-node weight w = 0.9^k2u + 1 - 0.9^u2k ----------------
__global__ void k_w(const void* __restrict__ k2u, const void* __restrict__ u2k) {
    int n = blockIdx.x * blockDim.x + threadIdx.x;
    int is64 = g_is64;
    if (n < NN) {
        float a = powf(0.9f, (float)load_idx(k2u, n, is64));
        float b = powf(0.9f, (float)load_idx(u2k, n, is64));
        g_w[n] = a + 1.0f - b;
    }
}

// ---------------- adjacency bitmap + degree ----------------
__global__ void k_adj(const void* __restrict__ ei) {
    int e = blockIdx.x * blockDim.x + threadIdx.x;
    int is64 = g_is64;
    if (e < NE) {
        int i = load_idx(ei, e, is64);
        int j = load_idx(ei, NE + e, is64);
        unsigned b1 = (unsigned)i * NN + (unsigned)j;
        atomicOr(&g_adj[b1 >> 5], 1u << (b1 & 31));
        unsigned b2 = (unsigned)j * NN + (unsigned)i;
        atomicOr(&g_adj[b2 >> 5], 1u << (b2 & 31));
        atomicAdd(&g_deg[i], 1.0f);
    }
}

// ---------------- cov = zm^T @ zm  (split-K, 64x64 tiles) ----------------
__global__ void k_cov(const float* __restrict__ z) {
    __shared__ float sA[16][68];
    __shared__ float sB[16][68];
    int i0 = blockIdx.x * 64, j0 = blockIdx.y * 64, r0 = blockIdx.z * 512;
    int tid = threadIdx.x;
    int tx = tid & 15, ty = tid >> 4;
    int col = tid & 63;
    int kb = tid >> 6;
    float meanA = g_mean[i0 + col];
    float meanB = g_mean[j0 + col];
    float acc[4][4] = {};
    for (int rr = 0; rr < 512; rr += 16) {
        __syncthreads();
        #pragma unroll
        for (int l = 0; l < 4; ++l) {
            int kk = kb * 4 + l;
            int r = r0 + rr + kk;
            sA[kk][col] = z[r * FF + i0 + col] - meanA;
            sB[kk][col] = z[r * FF + j0 + col] - meanB;
        }
        __syncthreads();
        #pragma unroll
        for (int kk = 0; kk < 16; ++kk) {
            float a[4], b[4];
            #pragma unroll
            for (int u = 0; u < 4; ++u) a[u] = sA[kk][tx * 4 + u];
            #pragma unroll
            for (int v = 0; v < 4; ++v) b[v] = sB[kk][ty * 4 + v];
            #pragma unroll
            for (int u = 0; u < 4; ++u)
                #pragma unroll
                for (int v = 0; v < 4; ++v) acc[u][v] += a[u] * b[v];
        }
    }
    #pragma unroll
    for (int u = 0; u < 4; ++u)
        #pragma unroll
        for (int v = 0; v < 4; ++v)
            atomicAdd(&g_cov[(i0 + tx * 4 + u) * FF + (j0 + ty * 4 + v)], acc[u][v]);
}

// ---------------- cor ----------------
__global__ void k_cor() {
    int idx = blockIdx.x * blockDim.x + threadIdx.x;
    int i = idx >> 8, j = idx & 255;
    float d = sqrtf(g_cov[i * FF + i]) * sqrtf(g_cov[j * FF + j]);
    float v = g_cov[idx] / d;
    if (v != v) v = 0.0f;
    v = fminf(1.0f, fmaxf(-1.0f, v));
    if (i == j) v = 0.0f;
    g_cor[idx] = v;
}

// ---------------- z2 = z + 0.01 * (w .* zm) @ cor ----------------
__global__ void k_z2(const float* __restrict__ z) {
    __shared__ float sA[16][132];
    __shared__ float sB[16][132];
    int r0 = blockIdx.x * 128, c0 = blockIdx.y * 128;
    int tid = threadIdx.x;
    int tx = tid & 15, ty = tid >> 4;
    float acc[8][8] = {};
    for (int k0 = 0; k0 < FF; k0 += 16) {
        __syncthreads();
        #pragma unroll
        for (int it = 0; it < 2; ++it) {
            int idx = tid + it * 256;
            int row = idx >> 2, kq = idx & 3;
            float4 zv = *(const float4*)(z + (r0 + row) * FF + k0 + kq * 4);
            float4 mv = *(const float4*)(g_mean + k0 + kq * 4);
            float wv = g_w[r0 + row];
            sA[kq * 4 + 0][row] = wv * (zv.x - mv.x);
            sA[kq * 4 + 1][row] = wv * (zv.y - mv.y);
            sA[kq * 4 + 2][row] = wv * (zv.z - mv.z);
            sA[kq * 4 + 3][row] = wv * (zv.w - mv.w);
            int kk = idx >> 5, nq = idx & 31;
            float4 bv = *(const float4*)(g_cor + (k0 + kk) * FF + c0 + nq * 4);
            *(float4*)&sB[kk][nq * 4] = bv;
        }
        __syncthreads();
        #pragma unroll
        for (int kk = 0; kk < 16; ++kk) {
            float4 a0 = *(const float4*)&sA[kk][ty * 8];
            float4 a1 = *(const float4*)&sA[kk][ty * 8 + 4];
            float4 b0 = *(const float4*)&sB[kk][tx * 8];
            float4 b1 = *(const float4*)&sB[kk][tx * 8 + 4];
            float a[8] = {a0.x, a0.y, a0.z, a0.w, a1.x, a1.y, a1.z, a1.w};
            float b[8] = {b0.x, b0.y, b0.z, b0.w, b1.x, b1.y, b1.z, b1.w};
            #pragma unroll
            for (int u = 0; u < 8; ++u)
                #pragma unroll
                for (int v = 0; v < 8; ++v) acc[u][v] += a[u] * b[v];
        }
    }
    #pragma unroll
    for (int u = 0; u < 8; ++u) {
        int r = r0 + ty * 8 + u;
        #pragma unroll
        for (int v = 0; v < 8; ++v) {
            int c = c0 + tx * 8 + v;
            g_z2[r * FF + c] = z[r * FF + c] + 0.01f * acc[u][v];
        }
    }
}

// ---------------- row norms + diag penalty + bf16 copy ----------------
__global__ void k_norm() {
    int gw = (blockIdx.x * blockDim.x + threadIdx.x) >> 5;
    int lane = threadIdx.x & 31;
    if (gw >= NN) return;
    const float4* p = (const float4*)(g_z2 + gw * FF);
    float4 a = p[lane * 2], b = p[lane * 2 + 1];
    // bf16 copy: 8 floats -> 8 bf16 (16B) per lane
    union { __nv_bfloat162 h[4]; uint4 u; } cv;
    cv.h[0] = __floats2bfloat162_rn(a.x, a.y);
    cv.h[1] = __floats2bfloat162_rn(a.z, a.w);
    cv.h[2] = __floats2bfloat162_rn(b.x, b.y);
    cv.h[3] = __floats2bfloat162_rn(b.z, b.w);
    *((uint4*)(g_z2h + gw * FF) + lane) = cv.u;

    float s = a.x * a.x + a.y * a.y + a.z * a.z + a.w * a.w
            + b.x * b.x + b.y * b.y + b.z * b.z + b.w * b.w;
    #pragma unroll
    for (int o = 16; o; o >>= 1) s += __shfl_down_sync(0xffffffffu, s, o);
    if (lane == 0) {
        g_invn[gw] = 1.0f / fmaxf(sqrtf(s), 1e-8f);
        unsigned bi = (unsigned)gw * NN + (unsigned)gw;
        unsigned bit = (g_adj[bi >> 5] >> (bi & 31)) & 1u;
        if (s > 0.8f && !bit) atomicAdd(&g_penalty, (double)s);
    }
}

// ---------------- per-edge cosine similarity ----------------
__global__ void k_edge(const void* __restrict__ ei) {
    int gw = (blockIdx.x * blockDim.x + threadIdx.x) >> 5;
    int lane = threadIdx.x & 31;
    if (gw >= NE) return;
    int is64 = g_is64;
    int i = load_idx(ei, gw, is64);
    int j = load_idx(ei, NE + gw, is64);
    const float4* pi = (const float4*)(g_z2 + i * FF);
    const float4* pj = (const float4*)(g_z2 + j * FF);
    float4 a0 = pi[lane * 2], a1 = pi[lane * 2 + 1];
    float4 b0 = pj[lane * 2], b1 = pj[lane * 2 + 1];
    float d = a0.x * b0.x + a0.y * b0.y + a0.z * b0.z + a0.w * b0.w
            + a1.x * b1.x + a1.y * b1.y + a1.z * b1.z + a1.w * b1.w;
    #pragma unroll
    for (int o = 16; o; o >>= 1) d += __shfl_down_sync(0xffffffffu, d, o);
    if (lane == 0) atomicAdd(&g_scores[i], d * g_invn[i] * g_invn[j]);
}

// ---------------- masked similarity GEMM: bf16 tensor-core version ----------------
__device__ __forceinline__ int cumt(int br) { return br * 64 - (br * (br - 1)) / 2; }

__device__ __forceinline__ void ldsm_x4(unsigned addr, unsigned& r0, unsigned& r1,
                                        unsigned& r2, unsigned& r3) {
    asm volatile("ldmatrix.sync.aligned.m8n8.x4.shared.b16 {%0,%1,%2,%3}, [%4];"
                 : "=r"(r0), "=r"(r1), "=r"(r2), "=r"(r3) : "r"(addr));
}

__device__ __forceinline__ void mma16816(float* d, const unsigned* a, const unsigned* b) {
    asm volatile(
        "mma.sync.aligned.m16n8k16.row.col.f32.bf16.bf16.f32 "
        "{%0,%1,%2,%3}, {%4,%5,%6,%7}, {%8,%9}, {%0,%1,%2,%3};"
        : "+f"(d[0]), "+f"(d[1]), "+f"(d[2]), "+f"(d[3])
        : "r"(a[0]), "r"(a[1]), "r"(a[2]), "r"(a[3]), "r"(b[0]), "r"(b[1]));
}

// dynamic smem: sA 32KB + sB 32KB (128 rows x 16 chunks of 16B, XOR-swizzled)
__global__ void __launch_bounds__(256, 2) k_sim() {
    extern __shared__ char dsm[];
    __shared__ unsigned sAdj[512];
    __shared__ float sRed[256];

    int t = blockIdx.x;
    int br = (int)(64.5f - sqrtf(64.5f * 64.5f - 2.0f * (float)t));
    if (br < 0) br = 0; if (br > 63) br = 63;
    while (br < 63 && cumt(br + 1) <= t) br++;
    while (br > 0 && cumt(br) > t) br--;
    int bc = br + (t - cumt(br));
    int r0 = br * 128, c0 = bc * 128;

    int tid = threadIdx.x;
    int lane = tid & 31;
    int warp = tid >> 5;
    int wm = warp & 3;        // 4 row blocks of 32
    int wn = warp >> 2;       // 2 col blocks of 64

    unsigned sbase = (unsigned)__cvta_generic_to_shared(dsm);
    unsigned aBase = sbase;
    unsigned bBase = sbase + 32768;

    float acc[2][8][4] = {};

    #pragma unroll
    for (int slab = 0; slab < 2; ++slab) {
        int ko = slab * 128;
        __syncthreads();
        // load 128x128(bf16) slabs of A and B, swizzled
        #pragma unroll
        for (int it = 0; it < 8; ++it) {
            int lin = tid + it * 256;              // 0..2047
            int r = lin >> 4, c = lin & 15;        // row, 16B chunk
            unsigned soff = (unsigned)(r * 256 + ((c ^ (r & 7)) << 4));
            uint4 va = *((const uint4*)(g_z2h + (r0 + r) * FF + ko) + c);
            uint4 vb = *((const uint4*)(g_z2h + (c0 + r) * FF + ko) + c);
            *(uint4*)(dsm + soff) = va;
            *(uint4*)(dsm + 32768 + soff) = vb;
        }
        __syncthreads();
        #pragma unroll
        for (int ks = 0; ks < 8; ++ks) {
            unsigned a[2][4];
            #pragma unroll
            for (int am = 0; am < 2; ++am) {
                int ra = wm * 32 + am * 16 + (lane & 15);
                int ca = 2 * ks + (lane >> 4);
                unsigned addr = aBase + ra * 256 + ((ca ^ (ra & 7)) << 4);
                ldsm_x4(addr, a[am][0], a[am][1], a[am][2], a[am][3]);
            }
            unsigned b[8][2];
            #pragma unroll
            for (int bn = 0; bn < 4; ++bn) {
                int rb = wn * 64 + bn * 16 + (lane & 7) + ((lane >> 4) << 3);
                int cb = 2 * ks + ((lane >> 3) & 1);
                unsigned addr = bBase + rb * 256 + ((cb ^ (rb & 7)) << 4);
                ldsm_x4(addr, b[2 * bn][0], b[2 * bn][1], b[2 * bn + 1][0], b[2 * bn + 1][1]);
            }
            #pragma unroll
            for (int am = 0; am < 2; ++am)
                #pragma unroll
                for (int nb = 0; nb < 8; ++nb)
                    mma16816(acc[am][nb], a[am], b[nb]);
        }
    }

    // adjacency words for this 128x128 tile
    for (int s2 = tid; s2 < 512; s2 += 256)
        sAdj[s2] = g_adj[(r0 + (s2 >> 2)) * (NN / 32) + (c0 >> 5) + (s2 & 3)];
    __syncthreads();

    bool diagBlk = (br == bc);
    float lsum = 0.0f;
    #pragma unroll
    for (int am = 0; am < 2; ++am) {
        #pragma unroll
        for (int nb = 0; nb < 8; ++nb) {
            #pragma unroll
            for (int e = 0; e < 4; ++e) {
                int rl = wm * 32 + am * 16 + (lane >> 2) + ((e >> 1) << 3);
                int cl = wn * 64 + nb * 8 + ((lane & 3) << 1) + (e & 1);
                float val = acc[am][nb][e];
                unsigned bit = (sAdj[rl * 4 + (cl >> 5)] >> (cl & 31)) & 1u;
                if (val > 0.8f && !bit && (!diagBlk || cl > rl)) lsum += val;
            }
        }
    }
    sRed[tid] = lsum;
    __syncthreads();
    for (int o = 128; o; o >>= 1) {
        if (tid < o) sRed[tid] += sRed[tid + o];
        __syncthreads();
    }
    if (tid == 0) atomicAdd(&g_penalty, 2.0 * (double)sRed[0]);
}

// ---------------- final scalar ----------------
__global__ void k_final(float* __restrict__ out) {
    __shared__ double sred[256];
    int tid = threadIdx.x;
    double s = 0.0;
    for (int n = tid; n < NN; n += 256) {
        float d = g_deg[n];
        if (d == 0.0f) d = 1.0f;
        s += (double)(g_scores[n] / d);
    }
    sred[tid] = s;
    __syncthreads();
    for (int o = 128; o; o >>= 1) {
        if (tid < o) sred[tid] += sred[tid + o];
        __syncthreads();
    }
    if (tid == 0) {
        double hom = -sred[0] / (double)NN;
        double pen = g_penalty / ((double)NN * (double)NN);
        out[0] = (float)(hom + pen);
    }
}

// ---------------- launch ----------------
extern "C" void kernel_launch(void* const* d_in, const int* in_sizes, int n_in,
                              void* d_out, int out_size) {
    const float* z   = (const float*)d_in[0];
    const void* ei   = d_in[2];
    const void* k2u  = d_in[3];
    const void* u2k  = d_in[4];
    float* out = (float*)d_out;

    cudaFuncSetAttribute(k_sim, cudaFuncAttributeMaxDynamicSharedMemorySize, 65536);

    k_detect<<<1, 256>>>((const unsigned*)ei);
    k_zero<<<2048, 256>>>();
    k_mean<<<128, 256>>>(z);
    k_meanfix<<<1, 256>>>();
    k_w<<<32, 256>>>(k2u, u2k);
    k_adj<<<NE / 256, 256>>>(ei);
    k_cov<<<dim3(4, 4, 16), 256>>>(z);
    k_cor<<<256, 256>>>();
    k_z2<<<dim3(64, 2), 256>>>(z);
    k_norm<<<NN / 8, 256>>>();
    k_edge<<<NE / 8, 256>>>(ei);
    k_sim<<<2080, 256, 65536>>>();
    k_final<<<1, 256>>>(out);
}

// round 7
// speedup vs baseline: 2.4115x; 1.0561x over previous
#include <cuda_runtime.h>
#include <cuda_bf16.h>
#include <math.h>

#define NN 8192
#define FF 256
#define NE 262144
#define ADJW (NN * (NN / 32))   // 2,097,152 words = 8 MB bitmap

// ---------------- scratch (device globals; no allocation allowed) ----------------
__device__ __align__(256) float    g_meansum[FF];
__device__ __align__(256) float    g_mean[FF];
__device__ __align__(256) float    g_mcor[FF];
__device__ __align__(256) float    g_cov[FF * FF];
__device__ __align__(256) float    g_cor[FF * FF];
__device__ __align__(256) __nv_bfloat16 g_corh[FF * FF];
__device__ __align__(256) float    g_w[NN];
__device__ __align__(256) float    g_z2[NN * FF];        // 8 MB fp32
__device__ __align__(256) __nv_bfloat16 g_zh[NN * FF];   // 4 MB bf16 of z
__device__ __align__(256) __nv_bfloat16 g_z2h[NN * FF];  // 4 MB bf16 of z2
__device__ __align__(256) float    g_invn[NN];
__device__ __align__(256) unsigned g_adj[ADJW];          // 8 MB adjacency bitmap
__device__ __align__(256) float    g_scores[NN];
__device__ __align__(256) float    g_deg[NN];
__device__ double g_penalty;
__device__ int    g_is64;

// ---------------- index dtype detection (int32 vs int64) ----------------
__global__ void k_detect(const unsigned* __restrict__ e) {
    unsigned acc = 0;
    for (int i = threadIdx.x; i < 2048; i += 256) acc |= e[2 * i + 1];
    int any = __syncthreads_or((int)(acc != 0));
    if (threadIdx.x == 0) g_is64 = any ? 0 : 1;
}

__device__ __forceinline__ int load_idx(const void* p, int k, int is64) {
    return is64 ? (int)((const long long*)p)[k] : ((const int*)p)[k];
}

// ---------------- zero scratch ----------------
__global__ void k_zero() {
    int idx = blockIdx.x * blockDim.x + threadIdx.x;
    int stride = gridDim.x * blockDim.x;
    for (int i = idx; i < ADJW; i += stride) g_adj[i] = 0u;
    for (int i = idx; i < FF * FF; i += stride) g_cov[i] = 0.0f;
    for (int i = idx; i < NN; i += stride) { g_scores[i] = 0.0f; g_deg[i] = 0.0f; }
    for (int i = idx; i < FF; i += stride) g_meansum[i] = 0.0f;
    if (idx == 0) g_penalty = 0.0;
}

// ---------------- fused: column sums + z -> bf16 ----------------
__global__ void k_meanzh(const float* __restrict__ z) {
    int f = threadIdx.x;
    int r0 = blockIdx.x * 64;
    float s = 0.0f;
    #pragma unroll 8
    for (int r = 0; r < 64; ++r) {
        float v = z[(r0 + r) * FF + f];
        s += v;
        g_zh[(r0 + r) * FF + f] = __float2bfloat16(v);
    }
    atomicAdd(&g_meansum[f], s);
}

__global__ void k_meanfix() {
    g_mean[threadIdx.x] = g_meansum[threadIdx.x] * (1.0f / (float)NN);
}

// ---------------- per-node weight ----------------
__global__ void k_w(const void* __restrict__ k2u, const void* __restrict__ u2k) {
    int n = blockIdx.x * blockDim.x + threadIdx.x;
    int is64 = g_is64;
    if (n < NN) {
        float a = powf(0.9f, (float)load_idx(k2u, n, is64));
        float b = powf(0.9f, (float)load_idx(u2k, n, is64));
        g_w[n] = a + 1.0f - b;
    }
}

// ---------------- adjacency bitmap + degree ----------------
__global__ void k_adj(const void* __restrict__ ei) {
    int e = blockIdx.x * blockDim.x + threadIdx.x;
    int is64 = g_is64;
    if (e < NE) {
        int i = load_idx(ei, e, is64);
        int j = load_idx(ei, NE + e, is64);
        unsigned b1 = (unsigned)i * NN + (unsigned)j;
        atomicOr(&g_adj[b1 >> 5], 1u << (b1 & 31));
        unsigned b2 = (unsigned)j * NN + (unsigned)i;
        atomicOr(&g_adj[b2 >> 5], 1u << (b2 & 31));
        atomicAdd(&g_deg[i], 1.0f);
    }
}

// ---------------- cov = zm^T @ zm  (upper-triangle tile pairs only) ----------------
__global__ void k_cov(const float* __restrict__ z) {
    if (blockIdx.x > blockIdx.y) return;           // symmetric: skip lower pairs
    __shared__ float sA[16][68];
    __shared__ float sB[16][68];
    int i0 = blockIdx.x * 64, j0 = blockIdx.y * 64, r0 = blockIdx.z * 512;
    int tid = threadIdx.x;
    int tx = tid & 15, ty = tid >> 4;
    int col = tid & 63;
    int kb = tid >> 6;
    float meanA = g_mean[i0 + col];
    float meanB = g_mean[j0 + col];
    float acc[4][4] = {};
    for (int rr = 0; rr < 512; rr += 16) {
        __syncthreads();
        #pragma unroll
        for (int l = 0; l < 4; ++l) {
            int kk = kb * 4 + l;
            int r = r0 + rr + kk;
            sA[kk][col] = z[r * FF + i0 + col] - meanA;
            sB[kk][col] = z[r * FF + j0 + col] - meanB;
        }
        __syncthreads();
        #pragma unroll
        for (int kk = 0; kk < 16; ++kk) {
            float a[4], b[4];
            #pragma unroll
            for (int u = 0; u < 4; ++u) a[u] = sA[kk][tx * 4 + u];
            #pragma unroll
            for (int v = 0; v < 4; ++v) b[v] = sB[kk][ty * 4 + v];
            #pragma unroll
            for (int u = 0; u < 4; ++u)
                #pragma unroll
                for (int v = 0; v < 4; ++v) acc[u][v] += a[u] * b[v];
        }
    }
    #pragma unroll
    for (int u = 0; u < 4; ++u)
        #pragma unroll
        for (int v = 0; v < 4; ++v)
            atomicAdd(&g_cov[(i0 + tx * 4 + u) * FF + (j0 + ty * 4 + v)], acc[u][v]);
}

// ---------------- cor (fp32 + bf16), reading cov upper triangle ----------------
__global__ void k_cor() {
    int idx = blockIdx.x * blockDim.x + threadIdx.x;
    int i = idx >> 8, j = idx & 255;
    int a = min(i, j), b = max(i, j);
    float d = sqrtf(g_cov[i * FF + i]) * sqrtf(g_cov[j * FF + j]);
    float v = g_cov[a * FF + b] / d;
    if (v != v) v = 0.0f;
    v = fminf(1.0f, fmaxf(-1.0f, v));
    if (i == j) v = 0.0f;
    g_cor[idx] = v;
    g_corh[idx] = __float2bfloat16(v);
}

// ---------------- mcor[c] = sum_k mean[k] * cor[k,c] ----------------
__global__ void k_mcor() {
    int c = threadIdx.x;
    float s = 0.0f;
    for (int k = 0; k < FF; ++k) s += g_mean[k] * g_cor[k * FF + c];
    g_mcor[c] = s;
}

// ---------------- MMA helpers ----------------
__device__ __forceinline__ void ldsm_x4(unsigned addr, unsigned& r0, unsigned& r1,
                                        unsigned& r2, unsigned& r3) {
    asm volatile("ldmatrix.sync.aligned.m8n8.x4.shared.b16 {%0,%1,%2,%3}, [%4];"
                 : "=r"(r0), "=r"(r1), "=r"(r2), "=r"(r3) : "r"(addr));
}

__device__ __forceinline__ void mma16816(float* d, const unsigned* a, const unsigned* b) {
    asm volatile(
        "mma.sync.aligned.m16n8k16.row.col.f32.bf16.bf16.f32 "
        "{%0,%1,%2,%3}, {%4,%5,%6,%7}, {%8,%9}, {%0,%1,%2,%3};"
        : "+f"(d[0]), "+f"(d[1]), "+f"(d[2]), "+f"(d[3])
        : "r"(a[0]), "r"(a[1]), "r"(a[2]), "r"(a[3]), "r"(b[0]), "r"(b[1]));
}

// ---------------- z2 = z + 0.01*w*(zh@corh - mcor) : bf16 tensor GEMM ----------------
__global__ void __launch_bounds__(256, 2) k_z2m(const float* __restrict__ z) {
    extern __shared__ char dsm[];
    int r0 = blockIdx.x * 128, c0 = blockIdx.y * 128;
    int tid = threadIdx.x;
    int lane = tid & 31;
    int warp = tid >> 5;
    int wm = warp & 3;
    int wn = warp >> 2;
    unsigned sbase = (unsigned)__cvta_generic_to_shared(dsm);
    unsigned aBase = sbase;
    unsigned bBase = sbase + 32768;
    float acc[2][8][4] = {};

    #pragma unroll
    for (int slab = 0; slab < 2; ++slab) {
        int ko = slab * 128;
        __syncthreads();
        #pragma unroll
        for (int it = 0; it < 8; ++it) {
            int lin = tid + it * 256;
            int r = lin >> 4, c = lin & 15;
            unsigned soff = (unsigned)(r * 256 + ((c ^ (r & 7)) << 4));
            uint4 va = *((const uint4*)(g_zh + (r0 + r) * FF + ko) + c);
            uint4 vb = *((const uint4*)(g_corh + (c0 + r) * FF + ko) + c);
            *(uint4*)(dsm + soff) = va;
            *(uint4*)(dsm + 32768 + soff) = vb;
        }
        __syncthreads();
        #pragma unroll
        for (int ks = 0; ks < 8; ++ks) {
            unsigned a[2][4];
            #pragma unroll
            for (int am = 0; am < 2; ++am) {
                int ra = wm * 32 + am * 16 + (lane & 15);
                int ca = 2 * ks + (lane >> 4);
                unsigned addr = aBase + ra * 256 + ((ca ^ (ra & 7)) << 4);
                ldsm_x4(addr, a[am][0], a[am][1], a[am][2], a[am][3]);
            }
            unsigned b[8][2];
            #pragma unroll
            for (int bn = 0; bn < 4; ++bn) {
                int rb = wn * 64 + bn * 16 + (lane & 7) + ((lane >> 4) << 3);
                int cb = 2 * ks + ((lane >> 3) & 1);
                unsigned addr = bBase + rb * 256 + ((cb ^ (rb & 7)) << 4);
                ldsm_x4(addr, b[2 * bn][0], b[2 * bn][1], b[2 * bn + 1][0], b[2 * bn + 1][1]);
            }
            #pragma unroll
            for (int am = 0; am < 2; ++am)
                #pragma unroll
                for (int nb = 0; nb < 8; ++nb)
                    mma16816(acc[am][nb], a[am], b[nb]);
        }
    }

    #pragma unroll
    for (int am = 0; am < 2; ++am) {
        #pragma unroll
        for (int nb = 0; nb < 8; ++nb) {
            #pragma unroll
            for (int e = 0; e < 4; ++e) {
                int rl = wm * 32 + am * 16 + (lane >> 2) + ((e >> 1) << 3);
                int cl = wn * 64 + nb * 8 + ((lane & 3) << 1) + (e & 1);
                int r = r0 + rl, c = c0 + cl;
                g_z2[r * FF + c] = z[r * FF + c]
                                 + 0.01f * g_w[r] * (acc[am][nb][e] - g_mcor[c]);
            }
        }
    }
}

// ---------------- row norms + diag penalty + bf16 copy ----------------
__global__ void k_norm() {
    int gw = (blockIdx.x * blockDim.x + threadIdx.x) >> 5;
    int lane = threadIdx.x & 31;
    if (gw >= NN) return;
    const float4* p = (const float4*)(g_z2 + gw * FF);
    float4 a = p[lane * 2], b = p[lane * 2 + 1];
    union { __nv_bfloat162 h[4]; uint4 u; } cv;
    cv.h[0] = __floats2bfloat162_rn(a.x, a.y);
    cv.h[1] = __floats2bfloat162_rn(a.z, a.w);
    cv.h[2] = __floats2bfloat162_rn(b.x, b.y);
    cv.h[3] = __floats2bfloat162_rn(b.z, b.w);
    *((uint4*)(g_z2h + gw * FF) + lane) = cv.u;

    float s = a.x * a.x + a.y * a.y + a.z * a.z + a.w * a.w
            + b.x * b.x + b.y * b.y + b.z * b.z + b.w * b.w;
    #pragma unroll
    for (int o = 16; o; o >>= 1) s += __shfl_down_sync(0xffffffffu, s, o);
    if (lane == 0) {
        g_invn[gw] = 1.0f / fmaxf(sqrtf(s), 1e-8f);
        unsigned bi = (unsigned)gw * NN + (unsigned)gw;
        unsigned bit = (g_adj[bi >> 5] >> (bi & 31)) & 1u;
        if (s > 0.8f && !bit) atomicAdd(&g_penalty, (double)s);
    }
}

// ---------------- per-edge cosine similarity (bf16 gathers) ----------------
__global__ void k_edge(const void* __restrict__ ei) {
    int gw = (blockIdx.x * blockDim.x + threadIdx.x) >> 5;
    int lane = threadIdx.x & 31;
    if (gw >= NE) return;
    int is64 = g_is64;
    int i = load_idx(ei, gw, is64);
    int j = load_idx(ei, NE + gw, is64);
    union { uint4 u; __nv_bfloat162 h[4]; } ua, ub;
    ua.u = *((const uint4*)(g_z2h + i * FF) + lane);
    ub.u = *((const uint4*)(g_z2h + j * FF) + lane);
    float d = 0.0f;
    #pragma unroll
    for (int q = 0; q < 4; ++q) {
        float2 fa = __bfloat1622float2(ua.h[q]);
        float2 fb = __bfloat1622float2(ub.h[q]);
        d += fa.x * fb.x + fa.y * fb.y;
    }
    #pragma unroll
    for (int o = 16; o; o >>= 1) d += __shfl_down_sync(0xffffffffu, d, o);
    if (lane == 0) atomicAdd(&g_scores[i], d * g_invn[i] * g_invn[j]);
}

// ---------------- masked similarity GEMM (bf16 tensor) ----------------
__device__ __forceinline__ int cumt(int br) { return br * 64 - (br * (br - 1)) / 2; }

__global__ void __launch_bounds__(256, 2) k_sim() {
    extern __shared__ char dsm[];
    __shared__ unsigned sAdj[512];
    __shared__ float sRed[256];

    int t = blockIdx.x;
    int br = (int)(64.5f - sqrtf(64.5f * 64.5f - 2.0f * (float)t));
    if (br < 0) br = 0; if (br > 63) br = 63;
    while (br < 63 && cumt(br + 1) <= t) br++;
    while (br > 0 && cumt(br) > t) br--;
    int bc = br + (t - cumt(br));
    int r0 = br * 128, c0 = bc * 128;

    int tid = threadIdx.x;
    int lane = tid & 31;
    int warp = tid >> 5;
    int wm = warp & 3;
    int wn = warp >> 2;

    // adjacency prefetch — latency hides under slab loads
    for (int s2 = tid; s2 < 512; s2 += 256)
        sAdj[s2] = g_adj[(r0 + (s2 >> 2)) * (NN / 32) + (c0 >> 5) + (s2 & 3)];

    unsigned sbase = (unsigned)__cvta_generic_to_shared(dsm);
    unsigned aBase = sbase;
    unsigned bBase = sbase + 32768;
    float acc[2][8][4] = {};

    #pragma unroll
    for (int slab = 0; slab < 2; ++slab) {
        int ko = slab * 128;
        __syncthreads();
        #pragma unroll
        for (int it = 0; it < 8; ++it) {
            int lin = tid + it * 256;
            int r = lin >> 4, c = lin & 15;
            unsigned soff = (unsigned)(r * 256 + ((c ^ (r & 7)) << 4));
            uint4 va = *((const uint4*)(g_z2h + (r0 + r) * FF + ko) + c);
            uint4 vb = *((const uint4*)(g_z2h + (c0 + r) * FF + ko) + c);
            *(uint4*)(dsm + soff) = va;
            *(uint4*)(dsm + 32768 + soff) = vb;
        }
        __syncthreads();
        #pragma unroll
        for (int ks = 0; ks < 8; ++ks) {
            unsigned a[2][4];
            #pragma unroll
            for (int am = 0; am < 2; ++am) {
                int ra = wm * 32 + am * 16 + (lane & 15);
                int ca = 2 * ks + (lane >> 4);
                unsigned addr = aBase + ra * 256 + ((ca ^ (ra & 7)) << 4);
                ldsm_x4(addr, a[am][0], a[am][1], a[am][2], a[am][3]);
            }
            unsigned b[8][2];
            #pragma unroll
            for (int bn = 0; bn < 4; ++bn) {
                int rb = wn * 64 + bn * 16 + (lane & 7) + ((lane >> 4) << 3);
                int cb = 2 * ks + ((lane >> 3) & 1);
                unsigned addr = bBase + rb * 256 + ((cb ^ (rb & 7)) << 4);
                ldsm_x4(addr, b[2 * bn][0], b[2 * bn][1], b[2 * bn + 1][0], b[2 * bn + 1][1]);
            }
            #pragma unroll
            for (int am = 0; am < 2; ++am)
                #pragma unroll
                for (int nb = 0; nb < 8; ++nb)
                    mma16816(acc[am][nb], a[am], b[nb]);
        }
    }

    bool diagBlk = (br == bc);
    float lsum = 0.0f;
    #pragma unroll
    for (int am = 0; am < 2; ++am) {
        #pragma unroll
        for (int nb = 0; nb < 8; ++nb) {
            #pragma unroll
            for (int e = 0; e < 4; ++e) {
                int rl = wm * 32 + am * 16 + (lane >> 2) + ((e >> 1) << 3);
                int cl = wn * 64 + nb * 8 + ((lane & 3) << 1) + (e & 1);
                float val = acc[am][nb][e];
                unsigned bit = (sAdj[rl * 4 + (cl >> 5)] >> (cl & 31)) & 1u;
                if (val > 0.8f && !bit && (!diagBlk || cl > rl)) lsum += val;
            }
        }
    }
    sRed[tid] = lsum;
    __syncthreads();
    for (int o = 128; o; o >>= 1) {
        if (tid < o) sRed[tid] += sRed[tid + o];
        __syncthreads();
    }
    if (tid == 0) atomicAdd(&g_penalty, 2.0 * (double)sRed[0]);
}

// ---------------- final scalar ----------------
__global__ void k_final(float* __restrict__ out) {
    __shared__ double sred[256];
    int tid = threadIdx.x;
    double s = 0.0;
    for (int n = tid; n < NN; n += 256) {
        float d = g_deg[n];
        if (d == 0.0f) d = 1.0f;
        s += (double)(g_scores[n] / d);
    }
    sred[tid] = s;
    __syncthreads();
    for (int o = 128; o; o >>= 1) {
        if (tid < o) sred[tid] += sred[tid + o];
        __syncthreads();
    }
    if (tid == 0) {
        double hom = -sred[0] / (double)NN;
        double pen = g_penalty / ((double)NN * (double)NN);
        out[0] = (float)(hom + pen);
    }
}

// ---------------- launch ----------------
extern "C" void kernel_launch(void* const* d_in, const int* in_sizes, int n_in,
                              void* d_out, int out_size) {
    const float* z   = (const float*)d_in[0];
    const void* ei   = d_in[2];
    const void* k2u  = d_in[3];
    const void* u2k  = d_in[4];
    float* out = (float*)d_out;

    cudaFuncSetAttribute(k_sim, cudaFuncAttributeMaxDynamicSharedMemorySize, 65536);
    cudaFuncSetAttribute(k_z2m, cudaFuncAttributeMaxDynamicSharedMemorySize, 65536);

    k_detect<<<1, 256>>>((const unsigned*)ei);
    k_zero<<<2048, 256>>>();
    k_meanzh<<<128, 256>>>(z);
    k_meanfix<<<1, 256>>>();
    k_w<<<32, 256>>>(k2u, u2k);
    k_adj<<<NE / 256, 256>>>(ei);
    k_cov<<<dim3(4, 4, 16), 256>>>(z);
    k_cor<<<256, 256>>>();
    k_mcor<<<1, 256>>>();
    k_z2m<<<dim3(64, 2), 256, 65536>>>(z);
    k_norm<<<NN / 8, 256>>>();
    k_edge<<<NE / 8, 256>>>(ei);
    k_sim<<<2080, 256, 65536>>>();
    k_final<<<1, 256>>>(out);
}

// round 9
// speedup vs baseline: 2.8409x; 1.1780x over previous
#include <cuda_runtime.h>
#include <cuda_bf16.h>
#include <math.h>
#include <stdint.h>

#define NN 8192
#define FF 256
#define NE 262144
#define ADJW (NN * (NN / 32))   // 2,097,152 words = 8 MB bitmap

// ---------------- scratch (device globals; no allocation allowed) ----------------
__device__ __align__(256) float    g_meansum[FF];
__device__ __align__(256) float    g_mean[FF];
__device__ __align__(256) float    g_mcor[FF];
__device__ __align__(256) float    g_cov[FF * FF];
__device__ __align__(256) float    g_cor[FF * FF];
__device__ __align__(256) __nv_bfloat16 g_corh[FF * FF];
__device__ __align__(256) float    g_w[NN];
__device__ __align__(256) float    g_z2[NN * FF];        // 8 MB fp32
__device__ __align__(256) __nv_bfloat16 g_zh[NN * FF];   // 4 MB bf16 of z
__device__ __align__(256) __nv_bfloat16 g_z2h[NN * FF];  // 4 MB bf16 of z2
__device__ __align__(256) float    g_invn[NN];
__device__ __align__(256) unsigned g_adj[ADJW];          // 8 MB adjacency bitmap
__device__ __align__(256) float    g_scores[NN];
__device__ __align__(256) float    g_deg[NN];
__device__ double g_penalty;
__device__ int    g_is64;

// ---------------- index dtype detection (int32 vs int64) ----------------
__global__ void k_detect(const unsigned* __restrict__ e) {
    unsigned acc = 0;
    for (int i = threadIdx.x; i < 2048; i += 256) acc |= e[2 * i + 1];
    int any = __syncthreads_or((int)(acc != 0));
    if (threadIdx.x == 0) g_is64 = any ? 0 : 1;
}

__device__ __forceinline__ int load_idx(const void* p, int k, int is64) {
    return is64 ? (int)((const long long*)p)[k] : ((const int*)p)[k];
}

// ---------------- zero scratch ----------------
__global__ void k_zero() {
    int idx = blockIdx.x * blockDim.x + threadIdx.x;
    int stride = gridDim.x * blockDim.x;
    for (int i = idx; i < ADJW; i += stride) g_adj[i] = 0u;
    for (int i = idx; i < FF * FF; i += stride) g_cov[i] = 0.0f;
    for (int i = idx; i < NN; i += stride) { g_scores[i] = 0.0f; g_deg[i] = 0.0f; }
    for (int i = idx; i < FF; i += stride) g_meansum[i] = 0.0f;
    if (idx == 0) g_penalty = 0.0;
}

// ---------------- fused: column sums + z -> bf16 ----------------
__global__ void k_meanzh(const float* __restrict__ z) {
    int f = threadIdx.x;
    int r0 = blockIdx.x * 64;
    float s = 0.0f;
    #pragma unroll 8
    for (int r = 0; r < 64; ++r) {
        float v = z[(r0 + r) * FF + f];
        s += v;
        g_zh[(r0 + r) * FF + f] = __float2bfloat16(v);
    }
    atomicAdd(&g_meansum[f], s);
}

__global__ void k_meanfix() {
    g_mean[threadIdx.x] = g_meansum[threadIdx.x] * (1.0f / (float)NN);
}

// ---------------- per-node weight ----------------
__global__ void k_w(const void* __restrict__ k2u, const void* __restrict__ u2k) {
    int n = blockIdx.x * blockDim.x + threadIdx.x;
    int is64 = g_is64;
    if (n < NN) {
        float a = powf(0.9f, (float)load_idx(k2u, n, is64));
        float b = powf(0.9f, (float)load_idx(u2k, n, is64));
        g_w[n] = a + 1.0f - b;
    }
}

// ---------------- adjacency bitmap + degree ----------------
__global__ void k_adj(const void* __restrict__ ei) {
    int e = blockIdx.x * blockDim.x + threadIdx.x;
    int is64 = g_is64;
    if (e < NE) {
        int i = load_idx(ei, e, is64);
        int j = load_idx(ei, NE + e, is64);
        unsigned b1 = (unsigned)i * NN + (unsigned)j;
        atomicOr(&g_adj[b1 >> 5], 1u << (b1 & 31));
        unsigned b2 = (unsigned)j * NN + (unsigned)i;
        atomicOr(&g_adj[b2 >> 5], 1u << (b2 & 31));
        atomicAdd(&g_deg[i], 1.0f);
    }
}

// ---------------- cov = zm^T @ zm  (upper-triangle tile pairs only) ----------------
__global__ void k_cov(const float* __restrict__ z) {
    if (blockIdx.x > blockIdx.y) return;
    __shared__ float sA[16][68];
    __shared__ float sB[16][68];
    int i0 = blockIdx.x * 64, j0 = blockIdx.y * 64, r0 = blockIdx.z * 512;
    int tid = threadIdx.x;
    int tx = tid & 15, ty = tid >> 4;
    int col = tid & 63;
    int kb = tid >> 6;
    float meanA = g_mean[i0 + col];
    float meanB = g_mean[j0 + col];
    float acc[4][4] = {};
    for (int rr = 0; rr < 512; rr += 16) {
        __syncthreads();
        #pragma unroll
        for (int l = 0; l < 4; ++l) {
            int kk = kb * 4 + l;
            int r = r0 + rr + kk;
            sA[kk][col] = z[r * FF + i0 + col] - meanA;
            sB[kk][col] = z[r * FF + j0 + col] - meanB;
        }
        __syncthreads();
        #pragma unroll
        for (int kk = 0; kk < 16; ++kk) {
            float a[4], b[4];
            #pragma unroll
            for (int u = 0; u < 4; ++u) a[u] = sA[kk][tx * 4 + u];
            #pragma unroll
            for (int v = 0; v < 4; ++v) b[v] = sB[kk][ty * 4 + v];
            #pragma unroll
            for (int u = 0; u < 4; ++u)
                #pragma unroll
                for (int v = 0; v < 4; ++v) acc[u][v] += a[u] * b[v];
        }
    }
    #pragma unroll
    for (int u = 0; u < 4; ++u)
        #pragma unroll
        for (int v = 0; v < 4; ++v)
            atomicAdd(&g_cov[(i0 + tx * 4 + u) * FF + (j0 + ty * 4 + v)], acc[u][v]);
}

// ---------------- cor (fp32 + bf16) ----------------
__global__ void k_cor() {
    int idx = blockIdx.x * blockDim.x + threadIdx.x;
    int i = idx >> 8, j = idx & 255;
    int a = min(i, j), b = max(i, j);
    float d = sqrtf(g_cov[i * FF + i]) * sqrtf(g_cov[j * FF + j]);
    float v = g_cov[a * FF + b] / d;
    if (v != v) v = 0.0f;
    v = fminf(1.0f, fmaxf(-1.0f, v));
    if (i == j) v = 0.0f;
    g_cor[idx] = v;
    g_corh[idx] = __float2bfloat16(v);
}

// ---------------- mcor[c] = sum_k mean[k] * cor[k,c]  (warp per column) ----------------
__global__ void k_mcor() {
    int warp = threadIdx.x >> 5;
    int lane = threadIdx.x & 31;
    int c = blockIdx.x * 8 + warp;
    float s = 0.0f;
    #pragma unroll
    for (int k = lane; k < FF; k += 32) s += g_mean[k] * g_cor[k * FF + c];
    #pragma unroll
    for (int o = 16; o; o >>= 1) s += __shfl_down_sync(0xffffffffu, s, o);
    if (lane == 0) g_mcor[c] = s;
}

// ---------------- MMA helpers ----------------
__device__ __forceinline__ void ldsm_x4(unsigned addr, unsigned& r0, unsigned& r1,
                                        unsigned& r2, unsigned& r3) {
    asm volatile("ldmatrix.sync.aligned.m8n8.x4.shared.b16 {%0,%1,%2,%3}, [%4];"
                 : "=r"(r0), "=r"(r1), "=r"(r2), "=r"(r3) : "r"(addr));
}

__device__ __forceinline__ void mma16816(float* d, const unsigned* a, const unsigned* b) {
    asm volatile(
        "mma.sync.aligned.m16n8k16.row.col.f32.bf16.bf16.f32 "
        "{%0,%1,%2,%3}, {%4,%5,%6,%7}, {%8,%9}, {%0,%1,%2,%3};"
        : "+f"(d[0]), "+f"(d[1]), "+f"(d[2]), "+f"(d[3])
        : "r"(a[0]), "r"(a[1]), "r"(a[2]), "r"(a[3]), "r"(b[0]), "r"(b[1]));
}

__device__ __forceinline__ void cp16(unsigned saddr, const void* gaddr) {
    asm volatile("cp.async.cg.shared.global [%0], [%1], 16;"
                 :: "r"(saddr), "l"(gaddr) : "memory");
}

// ---------------- z2 = z + 0.01*w*(zh@corh - mcor) : HMMA GEMM ----------------
__global__ void __launch_bounds__(256, 2) k_z2m(const float* __restrict__ z) {
    extern __shared__ char dsm[];
    int r0 = blockIdx.x * 128, c0 = blockIdx.y * 128;
    int tid = threadIdx.x;
    int lane = tid & 31;
    int warp = tid >> 5;
    int wm = warp & 3;
    int wn = warp >> 2;
    unsigned sbase = (unsigned)__cvta_generic_to_shared(dsm);
    unsigned aBase = sbase;
    unsigned bBase = sbase + 32768;
    float acc[2][8][4] = {};

    #pragma unroll
    for (int slab = 0; slab < 2; ++slab) {
        int ko = slab * 128;
        __syncthreads();
        #pragma unroll
        for (int it = 0; it < 8; ++it) {
            int lin = tid + it * 256;
            int r = lin >> 4, c = lin & 15;
            unsigned soff = (unsigned)(r * 256 + ((c ^ (r & 7)) << 4));
            uint4 va = *((const uint4*)(g_zh + (r0 + r) * FF + ko) + c);
            uint4 vb = *((const uint4*)(g_corh + (c0 + r) * FF + ko) + c);
            *(uint4*)(dsm + soff) = va;
            *(uint4*)(dsm + 32768 + soff) = vb;
        }
        __syncthreads();
        #pragma unroll
        for (int ks = 0; ks < 8; ++ks) {
            unsigned a[2][4];
            #pragma unroll
            for (int am = 0; am < 2; ++am) {
                int ra = wm * 32 + am * 16 + (lane & 15);
                int ca = 2 * ks + (lane >> 4);
                unsigned addr = aBase + ra * 256 + ((ca ^ (ra & 7)) << 4);
                ldsm_x4(addr, a[am][0], a[am][1], a[am][2], a[am][3]);
            }
            unsigned b[8][2];
            #pragma unroll
            for (int bn = 0; bn < 4; ++bn) {
                int rb = wn * 64 + bn * 16 + (lane & 7) + ((lane >> 4) << 3);
                int cb = 2 * ks + ((lane >> 3) & 1);
                unsigned addr = bBase + rb * 256 + ((cb ^ (rb & 7)) << 4);
                ldsm_x4(addr, b[2 * bn][0], b[2 * bn][1], b[2 * bn + 1][0], b[2 * bn + 1][1]);
            }
            #pragma unroll
            for (int am = 0; am < 2; ++am)
                #pragma unroll
                for (int nb = 0; nb < 8; ++nb)
                    mma16816(acc[am][nb], a[am], b[nb]);
        }
    }

    #pragma unroll
    for (int am = 0; am < 2; ++am) {
        #pragma unroll
        for (int nb = 0; nb < 8; ++nb) {
            #pragma unroll
            for (int e = 0; e < 4; ++e) {
                int rl = wm * 32 + am * 16 + (lane >> 2) + ((e >> 1) << 3);
                int cl = wn * 64 + nb * 8 + ((lane & 3) << 1) + (e & 1);
                int r = r0 + rl, c = c0 + cl;
                g_z2[r * FF + c] = z[r * FF + c]
                                 + 0.01f * g_w[r] * (acc[am][nb][e] - g_mcor[c]);
            }
        }
    }
}

// ---------------- row norms + diag penalty + bf16 copy ----------------
__global__ void k_norm() {
    int gw = (blockIdx.x * blockDim.x + threadIdx.x) >> 5;
    int lane = threadIdx.x & 31;
    if (gw >= NN) return;
    const float4* p = (const float4*)(g_z2 + gw * FF);
    float4 a = p[lane * 2], b = p[lane * 2 + 1];
    union { __nv_bfloat162 h[4]; uint4 u; } cv;
    cv.h[0] = __floats2bfloat162_rn(a.x, a.y);
    cv.h[1] = __floats2bfloat162_rn(a.z, a.w);
    cv.h[2] = __floats2bfloat162_rn(b.x, b.y);
    cv.h[3] = __floats2bfloat162_rn(b.z, b.w);
    *((uint4*)(g_z2h + gw * FF) + lane) = cv.u;

    float s = a.x * a.x + a.y * a.y + a.z * a.z + a.w * a.w
            + b.x * b.x + b.y * b.y + b.z * b.z + b.w * b.w;
    #pragma unroll
    for (int o = 16; o; o >>= 1) s += __shfl_down_sync(0xffffffffu, s, o);
    if (lane == 0) {
        g_invn[gw] = 1.0f / fmaxf(sqrtf(s), 1e-8f);
        unsigned bi = (unsigned)gw * NN + (unsigned)gw;
        unsigned bit = (g_adj[bi >> 5] >> (bi & 31)) & 1u;
        if (s > 0.8f && !bit) atomicAdd(&g_penalty, (double)s);
    }
}

// ---------------- per-edge cosine similarity (bf16 gathers) ----------------
__global__ void k_edge(const void* __restrict__ ei) {
    int gw = (blockIdx.x * blockDim.x + threadIdx.x) >> 5;
    int lane = threadIdx.x & 31;
    if (gw >= NE) return;
    int is64 = g_is64;
    int i = load_idx(ei, gw, is64);
    int j = load_idx(ei, NE + gw, is64);
    union { uint4 u; __nv_bfloat162 h[4]; } ua, ub;
    ua.u = *((const uint4*)(g_z2h + i * FF) + lane);
    ub.u = *((const uint4*)(g_z2h + j * FF) + lane);
    float d = 0.0f;
    #pragma unroll
    for (int q = 0; q < 4; ++q) {
        float2 fa = __bfloat1622float2(ua.h[q]);
        float2 fb = __bfloat1622float2(ub.h[q]);
        d += fa.x * fb.x + fa.y * fb.y;
    }
    #pragma unroll
    for (int o = 16; o; o >>= 1) d += __shfl_down_sync(0xffffffffu, d, o);
    if (lane == 0) atomicAdd(&g_scores[i], d * g_invn[i] * g_invn[j]);
}

// ---------------- masked similarity GEMM (HMMA + cp.async double buffer) ----------------
__device__ __forceinline__ int cumt(int br) { return br * 64 - (br * (br - 1)) / 2; }

// dynamic smem 64KB: A slabs at 0/16384, B slabs at 32768/49152
// each slab: 128 rows x 64 bf16 (128B rows, XOR-swizzled 16B chunks)
__global__ void __launch_bounds__(256, 2) k_sim() {
    extern __shared__ char dsm[];
    __shared__ unsigned sAdj[512];
    __shared__ float sRed[256];

    int t = blockIdx.x;
    int br = (int)(64.5f - sqrtf(64.5f * 64.5f - 2.0f * (float)t));
    if (br < 0) br = 0; if (br > 63) br = 63;
    while (br < 63 && cumt(br + 1) <= t) br++;
    while (br > 0 && cumt(br) > t) br--;
    int bc = br + (t - cumt(br));
    int r0 = br * 128, c0 = bc * 128;

    int tid = threadIdx.x;
    int lane = tid & 31;
    int warp = tid >> 5;
    int wm = warp & 3;
    int wn = warp >> 2;

    // adjacency prefetch — latency hides under first slab load
    for (int s2 = tid; s2 < 512; s2 += 256)
        sAdj[s2] = g_adj[(r0 + (s2 >> 2)) * (NN / 32) + (c0 >> 5) + (s2 & 3)];

    unsigned sbase = (unsigned)__cvta_generic_to_shared(dsm);

    // issue slab s into buffer bsel
    auto load_slab = [&](int s, int bsel) {
        unsigned aB = sbase + bsel * 16384;
        unsigned bB = sbase + 32768 + bsel * 16384;
        #pragma unroll
        for (int it = 0; it < 4; ++it) {
            int lin = tid + it * 256;          // 0..1023
            int r = lin >> 3, c = lin & 7;     // row, 16B chunk
            unsigned soff = (unsigned)(r * 128 + ((c ^ (r & 7)) << 4));
            cp16(aB + soff, g_z2h + (r0 + r) * FF + s * 64 + c * 8);
            cp16(bB + soff, g_z2h + (c0 + r) * FF + s * 64 + c * 8);
        }
        asm volatile("cp.async.commit_group;" ::: "memory");
    };

    float acc[2][8][4] = {};

    load_slab(0, 0);
    #pragma unroll
    for (int s = 0; s < 4; ++s) {
        if (s < 3) {
            load_slab(s + 1, (s + 1) & 1);
            asm volatile("cp.async.wait_group 1;" ::: "memory");
        } else {
            asm volatile("cp.async.wait_group 0;" ::: "memory");
        }
        __syncthreads();
        unsigned aBase = sbase + (s & 1) * 16384;
        unsigned bBase = sbase + 32768 + (s & 1) * 16384;
        #pragma unroll
        for (int ks = 0; ks < 4; ++ks) {
            unsigned a[2][4];
            #pragma unroll
            for (int am = 0; am < 2; ++am) {
                int ra = wm * 32 + am * 16 + (lane & 15);
                int ca = 2 * ks + (lane >> 4);
                unsigned addr = aBase + ra * 128 + ((ca ^ (ra & 7)) << 4);
                ldsm_x4(addr, a[am][0], a[am][1], a[am][2], a[am][3]);
            }
            unsigned b[8][2];
            #pragma unroll
            for (int bn = 0; bn < 4; ++bn) {
                int rb = wn * 64 + bn * 16 + (lane & 7) + ((lane >> 4) << 3);
                int cb = 2 * ks + ((lane >> 3) & 1);
                unsigned addr = bBase + rb * 128 + ((cb ^ (rb & 7)) << 4);
                ldsm_x4(addr, b[2 * bn][0], b[2 * bn][1], b[2 * bn + 1][0], b[2 * bn + 1][1]);
            }
            #pragma unroll
            for (int am = 0; am < 2; ++am)
                #pragma unroll
                for (int nb = 0; nb < 8; ++nb)
                    mma16816(acc[am][nb], a[am], b[nb]);
        }
        __syncthreads();   // buffer safe for reuse by next issue
    }

    bool diagBlk = (br == bc);
    float lsum = 0.0f;
    #pragma unroll
    for (int am = 0; am < 2; ++am) {
        #pragma unroll
        for (int nb = 0; nb < 8; ++nb) {
            #pragma unroll
            for (int e = 0; e < 4; ++e) {
                int rl = wm * 32 + am * 16 + (lane >> 2) + ((e >> 1) << 3);
                int cl = wn * 64 + nb * 8 + ((lane & 3) << 1) + (e & 1);
                float val = acc[am][nb][e];
                unsigned bit = (sAdj[rl * 4 + (cl >> 5)] >> (cl & 31)) & 1u;
                if (val > 0.8f && !bit && (!diagBlk || cl > rl)) lsum += val;
            }
        }
    }
    sRed[tid] = lsum;
    __syncthreads();
    for (int o = 128; o; o >>= 1) {
        if (tid < o) sRed[tid] += sRed[tid + o];
        __syncthreads();
    }
    if (tid == 0) atomicAdd(&g_penalty, 2.0 * (double)sRed[0]);
}

// ---------------- final scalar ----------------
__global__ void k_final(float* __restrict__ out) {
    __shared__ double sred[256];
    int tid = threadIdx.x;
    double s = 0.0;
    for (int n = tid; n < NN; n += 256) {
        float d = g_deg[n];
        if (d == 0.0f) d = 1.0f;
        s += (double)(g_scores[n] / d);
    }
    sred[tid] = s;
    __syncthreads();
    for (int o = 128; o; o >>= 1) {
        if (tid < o) sred[tid] += sred[tid + o];
        __syncthreads();
    }
    if (tid == 0) {
        double hom = -sred[0] / (double)NN;
        double pen = g_penalty / ((double)NN * (double)NN);
        out[0] = (float)(hom + pen);
    }
}

// ---------------- launch ----------------
extern "C" void kernel_launch(void* const* d_in, const int* in_sizes, int n_in,
                              void* d_out, int out_size) {
    const float* z   = (const float*)d_in[0];
    const void* ei   = d_in[2];
    const void* k2u  = d_in[3];
    const void* u2k  = d_in[4];
    float* out = (float*)d_out;

    cudaFuncSetAttribute(k_sim, cudaFuncAttributeMaxDynamicSharedMemorySize, 65536);
    cudaFuncSetAttribute(k_z2m, cudaFuncAttributeMaxDynamicSharedMemorySize, 65536);

    k_detect<<<1, 256>>>((const unsigned*)ei);
    k_zero<<<2048, 256>>>();
    k_meanzh<<<128, 256>>>(z);
    k_meanfix<<<1, 256>>>();
    k_w<<<32, 256>>>(k2u, u2k);
    k_adj<<<NE / 256, 256>>>(ei);
    k_cov<<<dim3(4, 4, 16), 256>>>(z);
    k_cor<<<256, 256>>>();
    k_mcor<<<32, 256>>>();
    k_z2m<<<dim3(64, 2), 256, 65536>>>(z);
    k_norm<<<NN / 8, 256>>>();
    k_edge<<<NE / 8, 256>>>(ei);
    k_sim<<<2080, 256, 65536>>>();
    k_final<<<1, 256>>>(out);
}